// round 17
// baseline (speedup 1.0000x reference)
#include <cuda_runtime.h>
#include <cuda_fp16.h>

#define SEQ 4096
#define HID 1024
#define NCTA 32
#define NTHR 544             // 16 compute warps + 1 poller warp
#define EPSF 1e-12f

// Scratch (allocation-free rule: __device__ globals)
__device__ float g_Xn[SEQ * HID];              // normalized embeddings
__device__ float g_P[SEQ * HID];               // W_hi @ x_t + b, precomputed
// tagged h double buffer: one u64 per ROW-PAIR: hi32 = tag, lo32 = fp16x2 (rows 2s, 2s+1)
__device__ unsigned long long g_H16[2][HID / 2];

// ---------------- weak L2-cached ld/st (fast path) ----------------
__device__ __forceinline__ void ld_cg_v2(const unsigned long long* p,
                                         unsigned long long& a, unsigned long long& b) {
    asm volatile("ld.global.cg.v2.u64 {%0,%1}, [%2];" : "=l"(a), "=l"(b) : "l"(p) : "memory");
}
__device__ __forceinline__ void st_cg(unsigned long long* p, unsigned long long v) {
    asm volatile("st.global.cg.u64 [%0], %1;" :: "l"(p), "l"(v) : "memory");
}
// ---------------- strong relaxed load (progress-guarantee fallback only) ----------------
__device__ __forceinline__ unsigned long long ld_rlx(const unsigned long long* p) {
    unsigned long long v;
    asm volatile("ld.relaxed.gpu.global.u64 %0, [%1];" : "=l"(v) : "l"(p) : "memory");
    return v;
}

// ---------------- f32x2 packed helpers ----------------
__device__ __forceinline__ unsigned long long packff(float a, float b) {
    unsigned long long r;
    asm("mov.b64 %0, {%1,%2};" : "=l"(r) : "r"(__float_as_uint(a)), "r"(__float_as_uint(b)));
    return r;
}
__device__ __forceinline__ void fma2(unsigned long long& acc, unsigned long long w,
                                     unsigned long long h) {
    asm("fma.rn.f32x2 %0, %1, %2, %0;" : "+l"(acc) : "l"(w), "l"(h));
}
__device__ __forceinline__ float sum2(unsigned long long a, unsigned long long b) {
    unsigned long long s;
    asm("add.rn.f32x2 %0, %1, %2;" : "=l"(s) : "l"(a), "l"(b));
    unsigned lo, hi;
    asm("mov.b64 {%0,%1}, %2;" : "=r"(lo), "=r"(hi) : "l"(s));
    return __uint_as_float(lo) + __uint_as_float(hi);
}

// ---------------- fast tanh: 1 - 2/(e^{2x}+1) via ex2/rcp approx ----------------
__device__ __forceinline__ float fast_tanh(float x) {
    float e;
    asm("ex2.approx.f32 %0, %1;" : "=f"(e) : "f"(x * 2.8853900817779268f)); // 2*log2(e)
    float r;
    asm("rcp.approx.f32 %0, %1;" : "=f"(r) : "f"(e + 1.0f));
    return fmaf(-2.0f, r, 1.0f);
}

// ---------------- fp16x2 <-> float packing ----------------
__device__ __forceinline__ unsigned pack_h2(float a, float b) {
    __half2 h = __floats2half2_rn(a, b);
    return *reinterpret_cast<unsigned*>(&h);
}
__device__ __forceinline__ float2 unpack_h2(unsigned u) {
    __half2 h = *reinterpret_cast<__half2*>(&u);
    return __half22float2(h);
}

// ---------------- named barriers (ids 1..3, NTHR arrivals) ----------------
__device__ __forceinline__ void bar_sync(int id) {
    asm volatile("bar.sync %0, %1;" :: "r"(id), "n"(NTHR) : "memory");
}

// ---------------- init: h0 -> out[0], tagged fp16 buf[0] (tag 1), clear buf[1] ----------------
__global__ __launch_bounds__(512) void init_kernel(const float* __restrict__ h0,
                                                   float* __restrict__ out) {
    int i = threadIdx.x;                        // 512 threads: one row-pair each
    float a = h0[2 * i], b = h0[2 * i + 1];
    out[2 * i] = a; out[2 * i + 1] = b;
    g_H16[0][i] = (1ull << 32) | (unsigned long long)pack_h2(a, b);
    g_H16[1][i] = 0ull;
}

// ---------------- embedding + L2 normalize ----------------
__global__ __launch_bounds__(256) void embed_kernel(const int* __restrict__ src,
                                                    const float* __restrict__ W) {
    const int t   = blockIdx.x;
    const int tid = threadIdx.x;
    const float4* row = reinterpret_cast<const float4*>(W) + (size_t)src[t] * (HID / 4);
    float4 v = row[tid];
    float s = v.x * v.x + v.y * v.y + v.z * v.z + v.w * v.w;
    #pragma unroll
    for (int o = 16; o; o >>= 1) s += __shfl_xor_sync(0xffffffffu, s, o);
    __shared__ float red[8];
    if ((tid & 31) == 0) red[tid >> 5] = s;
    __syncthreads();
    float tot = red[0] + red[1] + red[2] + red[3] + red[4] + red[5] + red[6] + red[7];
    float rn = 1.0f / fmaxf(sqrtf(tot), EPSF);
    float4 o4 = make_float4(v.x * rn, v.y * rn, v.z * rn, v.w * rn);
    reinterpret_cast<float4*>(g_Xn)[(size_t)t * (HID / 4) + tid] = o4;
}

// ---------------- GEMM: g_P[m][n] = sum_k g_Xn[m][k] * W_hi[n][k] + b[n] ----------------
#define BM 128
#define BN 64
#define BK 32
__global__ __launch_bounds__(256) void gemm_kernel(const float* __restrict__ Bw,
                                                   const float* __restrict__ bias) {
    __shared__ float As[BK][BM + 4];
    __shared__ float Bs[BK][BN + 4];
    const int tid = threadIdx.x;
    const int m0 = blockIdx.y * BM;
    const int n0 = blockIdx.x * BN;
    const int ty = tid >> 4;
    const int tx = tid & 15;

    float acc[8][4];
    #pragma unroll
    for (int i = 0; i < 8; i++)
        #pragma unroll
        for (int j = 0; j < 4; j++) acc[i][j] = 0.0f;

    for (int k0 = 0; k0 < HID; k0 += BK) {
        #pragma unroll
        for (int i = 0; i < 4; i++) {
            int idx = tid + i * 256;
            int r = idx >> 3;
            int kq = idx & 7;
            float4 f = reinterpret_cast<const float4*>(g_Xn)[(size_t)(m0 + r) * (HID / 4) + (k0 >> 2) + kq];
            As[kq * 4 + 0][r] = f.x;
            As[kq * 4 + 1][r] = f.y;
            As[kq * 4 + 2][r] = f.z;
            As[kq * 4 + 3][r] = f.w;
        }
        #pragma unroll
        for (int i = 0; i < 2; i++) {
            int idx = tid + i * 256;
            int r = idx >> 3;
            int kq = idx & 7;
            float4 f = reinterpret_cast<const float4*>(Bw)[(size_t)(n0 + r) * (HID / 4) + (k0 >> 2) + kq];
            Bs[kq * 4 + 0][r] = f.x;
            Bs[kq * 4 + 1][r] = f.y;
            Bs[kq * 4 + 2][r] = f.z;
            Bs[kq * 4 + 3][r] = f.w;
        }
        __syncthreads();
        #pragma unroll
        for (int k = 0; k < BK; k++) {
            float4 a0 = *reinterpret_cast<const float4*>(&As[k][ty * 8]);
            float4 a1 = *reinterpret_cast<const float4*>(&As[k][ty * 8 + 4]);
            float4 b0 = *reinterpret_cast<const float4*>(&Bs[k][tx * 4]);
            float ar[8] = {a0.x, a0.y, a0.z, a0.w, a1.x, a1.y, a1.z, a1.w};
            float br[4] = {b0.x, b0.y, b0.z, b0.w};
            #pragma unroll
            for (int i = 0; i < 8; i++)
                #pragma unroll
                for (int j = 0; j < 4; j++)
                    acc[i][j] = fmaf(ar[i], br[j], acc[i][j]);
        }
        __syncthreads();
    }

    float4 bb = reinterpret_cast<const float4*>(bias)[(n0 >> 2) + tx];
    #pragma unroll
    for (int i = 0; i < 8; i++) {
        int m = m0 + ty * 8 + i;
        float4 o = make_float4(acc[i][0] + bb.x, acc[i][1] + bb.y,
                               acc[i][2] + bb.z, acc[i][3] + bb.w);
        reinterpret_cast<float4*>(g_P)[(size_t)m * (HID / 4) + (n0 >> 2) + tx] = o;
    }
}

// ---------------- persistent RNN: two-phase overlapped detect/compute ----------------
// 32 CTAs x 17 warps (544 thr). Warps 0-15 compute (warp w owns rows
// c*32+2w, c*32+2w+1); warp 16 = dedicated poller. Protocol (unchanged):
// one u64 per row-pair = [tag32 | fp16x2], weak .cg, distance-2 induction.
// Pipeline per step:
//   poller : sweep slots 0..255 -> stage raw -> bar1 -> sweep 256..511 ->
//            stage -> bar2 -> bar3 (PARKED during compute: R13 fix)
//   compute: bar1 -> partial dot k=0..3 (overlaps poller's half1 sweep) ->
//            bar2 -> dot k=4..7 + reduce + tanh + publish -> bar3
// All 544 threads hit bars 1,2,3 in identical order each iteration (no
// deadlock); strong relaxed fallback every 64 sweeps (progress guarantee).
__global__ __launch_bounds__(NTHR) void rnn_kernel(const float* __restrict__ Whh,
                                                   float* __restrict__ out) {
    __shared__ unsigned shq[2][HID / 2];         // 4 KB: [parity][fp16x2 per row-pair]
    const int tid  = threadIdx.x;
    const int warp = tid >> 5;
    const int lane = tid & 31;
    const unsigned shb0 = (unsigned)__cvta_generic_to_shared(&shq[0][0]);

    if (warp == 16) {
        // ---------------- DEDICATED POLLER WARP ----------------
        for (int t = 0; t < SEQ; ++t) {
            const unsigned tag = (unsigned)(t + 1);
            const int par = t & 1;
            const unsigned long long* base = &g_H16[par][0] + (lane << 1);
            const unsigned sb = shb0 + ((unsigned)par << 11) + ((unsigned)lane << 3);

            #pragma unroll
            for (int half = 0; half < 2; half++) {
                const int k0 = half * 4;
                unsigned long long s0[4], s1[4];
                int spins = 0;
                for (;;) {
                    #pragma unroll
                    for (int k = 0; k < 4; k++)
                        ld_cg_v2(base + ((k0 + k) << 6), s0[k], s1[k]);
                    unsigned ok = 1u;
                    #pragma unroll
                    for (int k = 0; k < 4; k++)
                        ok &= (unsigned)((unsigned)(s0[k] >> 32) == tag) &
                              (unsigned)((unsigned)(s1[k] >> 32) == tag);
                    if (ok) break;
                    if ((++spins & 63) == 0) {     // rare strong fallback (progress)
                        unsigned ok2 = 1u;
                        #pragma unroll
                        for (int k = 0; k < 4; k++) {
                            s0[k] = ld_rlx(base + ((k0 + k) << 6));
                            s1[k] = ld_rlx(base + ((k0 + k) << 6) + 1);
                            ok2 &= (unsigned)((unsigned)(s0[k] >> 32) == tag) &
                                   (unsigned)((unsigned)(s1[k] >> 32) == tag);
                        }
                        if (ok2) break;
                    }
                }
                // stage raw fp16x2 words (4x st.shared.v2.u32)
                #pragma unroll
                for (int k = 0; k < 4; k++) {
                    asm volatile("st.shared.v2.u32 [%0], {%1,%2};"
                                 :: "r"(sb + ((unsigned)(k0 + k) << 8)),
                                    "r"((unsigned)s0[k]), "r"((unsigned)s1[k]));
                }
                bar_sync(1 + half);                // bar1 after half0, bar2 after half1
            }
            bar_sync(3);                           // park during compute (R13 fix)
        }
        return;
    }

    // ---------------- COMPUTE WARPS (0-15) ----------------
    const int rowA = (blockIdx.x << 5) + (warp << 1);
    const int rowB = rowA + 1;
    const int myslot = (blockIdx.x << 4) + warp;   // publish slot = rowA/2

    // weights for both rows as packed f32x2 (16 u64 per row = 64 regs total)
    unsigned long long wA[16], wB[16];
    {
        const float4* wra = reinterpret_cast<const float4*>(Whh) + (size_t)rowA * (HID / 4);
        const float4* wrb = wra + (HID / 4);
        #pragma unroll
        for (int k = 0; k < 8; k++) {
            float4 a = wra[lane + (k << 5)];
            float4 b = wrb[lane + (k << 5)];
            wA[2 * k] = packff(a.x, a.y); wA[2 * k + 1] = packff(a.z, a.w);
            wB[2 * k] = packff(b.x, b.y); wB[2 * k + 1] = packff(b.z, b.w);
        }
    }

    float pa = g_P[rowA], pb = g_P[rowB];

    for (int t = 0; t < SEQ; ++t) {
        const int par = t & 1;

        // prefetch next-step P (independent of h)
        float pan = 0.f, pbn = 0.f;
        if (t + 1 < SEQ) {
            pan = g_P[(size_t)(t + 1) * HID + rowA];
            pbn = g_P[(size_t)(t + 1) * HID + rowB];
        }

        const unsigned hb = shb0 + ((unsigned)par << 11);
        unsigned long long aA0 = 0ull, aA1 = 0ull, aB0 = 0ull, aB1 = 0ull;

        bar_sync(1);                               // half0 staged

        #pragma unroll
        for (int k = 0; k < 4; k++) {              // partial dot on h[0:512]
            unsigned w0, w1;
            asm volatile("ld.shared.v2.u32 {%0,%1}, [%2];"
                         : "=r"(w0), "=r"(w1)
                         : "r"(hb + ((unsigned)(lane + (k << 5)) << 3)));
            float2 f01 = unpack_h2(w0);
            float2 f23 = unpack_h2(w1);
            unsigned long long h01 = packff(f01.x, f01.y);
            unsigned long long h23 = packff(f23.x, f23.y);
            fma2(aA0, wA[2 * k], h01); fma2(aA1, wA[2 * k + 1], h23);
            fma2(aB0, wB[2 * k], h01); fma2(aB1, wB[2 * k + 1], h23);
        }

        bar_sync(2);                               // half1 staged

        #pragma unroll
        for (int k = 4; k < 8; k++) {              // rest of the dot
            unsigned w0, w1;
            asm volatile("ld.shared.v2.u32 {%0,%1}, [%2];"
                         : "=r"(w0), "=r"(w1)
                         : "r"(hb + ((unsigned)(lane + (k << 5)) << 3)));
            float2 f01 = unpack_h2(w0);
            float2 f23 = unpack_h2(w1);
            unsigned long long h01 = packff(f01.x, f01.y);
            unsigned long long h23 = packff(f23.x, f23.y);
            fma2(aA0, wA[2 * k], h01); fma2(aA1, wA[2 * k + 1], h23);
            fma2(aB0, wB[2 * k], h01); fma2(aB1, wB[2 * k + 1], h23);
        }
        float sa = sum2(aA0, aA1);
        float sb = sum2(aB0, aB1);
        #pragma unroll
        for (int o = 16; o; o >>= 1) {
            sa += __shfl_xor_sync(0xffffffffu, sa, o);
            sb += __shfl_xor_sync(0xffffffffu, sb, o);
        }

        // parallel tanh: lane0 -> row A, lane1 -> row B; lane0 publishes both
        float s  = (lane == 1) ? (sb + pb) : (sa + pa);
        float hv = fast_tanh(s);
        float hB = __shfl_sync(0xffffffffu, hv, 1);
        if (lane == 0) {
            unsigned long long wv = ((unsigned long long)(unsigned)(t + 2) << 32)
                                  | (unsigned long long)pack_h2(hv, hB);
            st_cg(&g_H16[(t + 1) & 1][myslot], wv);
            reinterpret_cast<float2*>(out + (size_t)(t + 1) * HID)[myslot] =
                make_float2(hv, hB);
        }
        pa = pan; pb = pbn;

        bar_sync(3);                               // releases poller for next step
    }
}

// ---------------- launch ----------------
extern "C" void kernel_launch(void* const* d_in, const int* in_sizes, int n_in,
                              void* d_out, int out_size) {
    const int*   src  = (const int*)  d_in[0];  // [4096]
    const float* W    = (const float*)d_in[1];  // [32000,1024]
    const float* h0   = (const float*)d_in[2];  // [1024]
    const float* W_hi = (const float*)d_in[3];  // [1024,1024]
    const float* W_hh = (const float*)d_in[4];  // [1024,1024]
    const float* b    = (const float*)d_in[5];  // [1024]
    float* out = (float*)d_out;                 // [4097,1024]

    init_kernel<<<1, 512>>>(h0, out);
    embed_kernel<<<SEQ, 256>>>(src, W);
    gemm_kernel<<<dim3(HID / BN, SEQ / BM), 256>>>(W_hi, b);
    rnn_kernel<<<NCTA, NTHR>>>(W_hh, out);
}